// round 2
// baseline (speedup 1.0000x reference)
#include <cuda_runtime.h>
#include <math.h>

// ---------------- problem constants ----------------
#define T_STEPS 2048
#define BATCH   64
#define IN_DIM  256
#define HID     512
#define NCTA    128      // 512 hidden units / 4 per CTA; all resident on 152-SM GB300
#define NTHREADS 256     // 8 warps, K-split across warps
#define NWARP   8

// SMEM row strides (floats), padded for bank behavior + 16B alignment
#define S1 772           // Wcat1: 768 cols (W_ih1 | W_hh1)
#define S2 1028          // Wcat2: 1024 cols (W_ih2 | W_hh2)

// dynamic smem layout (in floats)
//  ws1   : 16*S1      = 12352
//  ws2   : 16*S2      = 16448
//  stage : 8*16*64    = 8192
//  bias1 : 16, bias2 : 16, c1 : 256, c2 : 256
#define SMEM_FLOATS (16*S1 + 16*S2 + 8*16*64 + 16 + 16 + 256 + 256)

// ---------------- device scratch (static; no runtime allocation) ----------------
__device__ float g_h1slot[2][BATCH * HID];                     // double-buffered layer-1 h
__device__ float g_h2all[(size_t)T_STEPS * BATCH * HID];       // layer-2 h for all t (256MB)
__device__ unsigned g_count = 0;                               // barrier arrivals (self-resetting)
__device__ unsigned g_sense = 0;                               // barrier epoch (monotonic)

// ---------------- helpers ----------------
__device__ __forceinline__ unsigned ld_acq(unsigned* p) {
    unsigned v;
    asm volatile("ld.acquire.gpu.u32 %0, [%1];" : "=r"(v) : "l"(p));
    return v;
}

// packed fp32x2 FMA (FFMA2): 2 fp32 MACs/lane/inst -> 2x the FFMA-3reg rate
__device__ __forceinline__ void fma2(unsigned long long& d,
                                     unsigned long long a,
                                     unsigned long long b) {
    asm("fma.rn.f32x2 %0, %1, %2, %0;" : "+l"(d) : "l"(a), "l"(b));
}

// grid-wide barrier: sense-reversing, deterministic across graph replays
__device__ __forceinline__ void grid_barrier() {
    __syncthreads();
    if (threadIdx.x == 0) {
        unsigned s0 = ld_acq(&g_sense);
        __threadfence();                       // publish this CTA's global writes
        unsigned prev = atomicAdd(&g_count, 1);
        if (prev == NCTA - 1) {
            g_count = 0;                       // all arrived; reset for next use
            __threadfence();
            atomicAdd(&g_sense, 1);            // release
        } else {
            while (ld_acq(&g_sense) == s0) { } // acquire on release
        }
    }
    __syncthreads();
}

// accumulate: acc[i][bb] += sum_k src[b][k] * W[lr][k] over this call's k-range.
// src: global, row stride RS floats, already offset to the column base.
// wsm: smem,   row stride WS floats, already offset to the column base.
// lane tile: rows lr = rg*4+i (i<4), batches b = bg*8+bb (bb<8); nkq float4-quads.
__device__ __forceinline__ void accum(unsigned long long acc[4][8],
                                      const float* __restrict__ src, int RS,
                                      const float* wsm, int WS,
                                      int nkq, int rg, int bg) {
    const ulonglong2* hp[8];
    const ulonglong2* wp[4];
#pragma unroll
    for (int bb = 0; bb < 8; bb++)
        hp[bb] = reinterpret_cast<const ulonglong2*>(src + (size_t)(bg * 8 + bb) * RS);
#pragma unroll
    for (int i = 0; i < 4; i++)
        wp[i] = reinterpret_cast<const ulonglong2*>(wsm + (size_t)(rg * 4 + i) * WS);

#pragma unroll 4
    for (int kq = 0; kq < nkq; kq++) {
        ulonglong2 w[4], h[8];
#pragma unroll
        for (int i = 0; i < 4; i++) w[i] = wp[i][kq];
#pragma unroll
        for (int bb = 0; bb < 8; bb++) h[bb] = hp[bb][kq];
#pragma unroll
        for (int i = 0; i < 4; i++) {
#pragma unroll
            for (int bb = 0; bb < 8; bb++) {
                fma2(acc[i][bb], h[bb].x, w[i].x);
                fma2(acc[i][bb], h[bb].y, w[i].y);
            }
        }
    }
}

__device__ __forceinline__ float sigf(float x) { return 1.0f / (1.0f + expf(-x)); }

// ---------------- persistent fused 2-layer LSTM scan ----------------
__global__ void __launch_bounds__(NTHREADS, 1)
lstm_persistent(const float* __restrict__ input,
                const float* __restrict__ Wih1, const float* __restrict__ Whh1,
                const float* __restrict__ bih1, const float* __restrict__ bhh1,
                const float* __restrict__ Wih2, const float* __restrict__ Whh2,
                const float* __restrict__ bih2, const float* __restrict__ bhh2) {
    extern __shared__ float sm[];
    float* ws1   = sm;                          // 16 x S1
    float* ws2   = ws1 + 16 * S1;               // 16 x S2
    float* stage = ws2 + 16 * S2;               // 8 x 16 x 64
    float* bias1 = stage + 8 * 16 * 64;         // 16
    float* bias2 = bias1 + 16;                  // 16
    float* c1    = bias2 + 16;                  // 256
    float* c2    = c1 + 256;                    // 256

    const int tid  = threadIdx.x;
    const int cb   = blockIdx.x;
    const int j0   = cb * 4;                    // this CTA's 4 hidden units
    const int wid  = tid >> 5;
    const int lane = tid & 31;
    const int bg   = lane & 7;                  // batch group (8 batches)
    const int rg   = lane >> 3;                 // row group == gate index (4 rows)

    // ---- load weights + biases into SMEM (once) ----
    for (int lr = 0; lr < 16; lr++) {
        int grow = (lr >> 2) * HID + j0 + (lr & 3);   // gate*512 + j
        const float* a = Wih1 + (size_t)grow * IN_DIM;
        const float* b = Whh1 + (size_t)grow * HID;
        const float* c = Wih2 + (size_t)grow * HID;
        const float* d = Whh2 + (size_t)grow * HID;
        for (int k = tid; k < IN_DIM; k += NTHREADS) ws1[lr * S1 + k]          = a[k];
        for (int k = tid; k < HID;    k += NTHREADS) ws1[lr * S1 + IN_DIM + k] = b[k];
        for (int k = tid; k < HID;    k += NTHREADS) ws2[lr * S2 + k]          = c[k];
        for (int k = tid; k < HID;    k += NTHREADS) ws2[lr * S2 + HID + k]    = d[k];
    }
    if (tid < 16) {
        int grow = (tid >> 2) * HID + j0 + (tid & 3);
        bias1[tid] = bih1[grow] + bhh1[grow];
        bias2[tid] = bih2[grow] + bhh2[grow];
    }
    c1[tid] = 0.0f;
    c2[tid] = 0.0f;
    __syncthreads();

    for (int t = 0; t < T_STEPS; t++) {
        // ================= phase A: layer 1 =================
        unsigned long long acc[4][8];
#pragma unroll
        for (int i = 0; i < 4; i++)
#pragma unroll
            for (int bb = 0; bb < 8; bb++) acc[i][bb] = 0ull;

        // x_t part: K=256, warp chunk 32 cols
        accum(acc, input + (size_t)t * BATCH * IN_DIM + wid * 32, IN_DIM,
              ws1 + wid * 32, S1, 8, rg, bg);
        // h1_{t-1} part: K=512, warp chunk 64 cols
        if (t > 0)
            accum(acc, g_h1slot[(t - 1) & 1] + wid * 64, HID,
                  ws1 + IN_DIM + wid * 64, S1, 16, rg, bg);

#pragma unroll
        for (int i = 0; i < 4; i++)
#pragma unroll
            for (int bb = 0; bb < 8; bb++) {
                unsigned long long a = acc[i][bb];
                stage[(wid * 16 + rg * 4 + i) * 64 + bg * 8 + bb] =
                    __uint_as_float((unsigned)a) + __uint_as_float((unsigned)(a >> 32));
            }
        __syncthreads();

        {   // elementwise: one (jj, b) per thread
            int jj = tid >> 6, b = tid & 63;
            float gv[4];
#pragma unroll
            for (int g = 0; g < 4; g++) {
                float s = bias1[g * 4 + jj];
#pragma unroll
                for (int w = 0; w < NWARP; w++) s += stage[(w * 16 + g * 4 + jj) * 64 + b];
                gv[g] = s;
            }
            float c = c1[tid];
            c = sigf(gv[1]) * c + sigf(gv[0]) * tanhf(gv[2]);
            float h = sigf(gv[3]) * tanhf(c);
            c1[tid] = c;
            g_h1slot[t & 1][b * HID + j0 + jj] = h;
        }
        grid_barrier();

        // ================= phase B: layer 2 =================
#pragma unroll
        for (int i = 0; i < 4; i++)
#pragma unroll
            for (int bb = 0; bb < 8; bb++) acc[i][bb] = 0ull;

        // h1_t part: K=512
        accum(acc, g_h1slot[t & 1] + wid * 64, HID,
              ws2 + wid * 64, S2, 16, rg, bg);
        // h2_{t-1} part: K=512
        if (t > 0)
            accum(acc, g_h2all + ((size_t)(t - 1) * BATCH) * HID + wid * 64, HID,
                  ws2 + HID + wid * 64, S2, 16, rg, bg);

#pragma unroll
        for (int i = 0; i < 4; i++)
#pragma unroll
            for (int bb = 0; bb < 8; bb++) {
                unsigned long long a = acc[i][bb];
                stage[(wid * 16 + rg * 4 + i) * 64 + bg * 8 + bb] =
                    __uint_as_float((unsigned)a) + __uint_as_float((unsigned)(a >> 32));
            }
        __syncthreads();

        {
            int jj = tid >> 6, b = tid & 63;
            float gv[4];
#pragma unroll
            for (int g = 0; g < 4; g++) {
                float s = bias2[g * 4 + jj];
#pragma unroll
                for (int w = 0; w < NWARP; w++) s += stage[(w * 16 + g * 4 + jj) * 64 + b];
                gv[g] = s;
            }
            float c = c2[tid];
            c = sigf(gv[1]) * c + sigf(gv[0]) * tanhf(gv[2]);
            float h = sigf(gv[3]) * tanhf(c);
            c2[tid] = c;
            g_h2all[((size_t)t * BATCH + b) * HID + j0 + jj] = h;
        }
        grid_barrier();
    }
}

// ---------------- output head: out[t,b] = sigmoid(h2 . W_out + b_out) ----------------
__global__ void __launch_bounds__(256)
out_kernel(const float* __restrict__ Wout, const float* __restrict__ bout,
           float* __restrict__ out) {
    int gw   = (blockIdx.x * blockDim.x + threadIdx.x) >> 5;  // one warp per (t,b)
    int lane = threadIdx.x & 31;
    if (gw >= T_STEPS * BATCH) return;
    const float* h = g_h2all + (size_t)gw * HID;
    float s = 0.0f;
#pragma unroll
    for (int g = 0; g < 4; g++) {
        float4 hv = *reinterpret_cast<const float4*>(h + g * 128 + lane * 4);
        float4 wv = *reinterpret_cast<const float4*>(Wout + g * 128 + lane * 4);
        s += hv.x * wv.x + hv.y * wv.y + hv.z * wv.z + hv.w * wv.w;
    }
#pragma unroll
    for (int o = 16; o > 0; o >>= 1) s += __shfl_xor_sync(0xffffffffu, s, o);
    if (lane == 0) out[gw] = 1.0f / (1.0f + expf(-(s + bout[0])));
}

// ---------------- launch ----------------
extern "C" void kernel_launch(void* const* d_in, const int* in_sizes, int n_in,
                              void* d_out, int out_size) {
    const float* input = (const float*)d_in[0];
    const float* Wih1  = (const float*)d_in[1];
    const float* Whh1  = (const float*)d_in[2];
    const float* bih1  = (const float*)d_in[3];
    const float* bhh1  = (const float*)d_in[4];
    const float* Wih2  = (const float*)d_in[5];
    const float* Whh2  = (const float*)d_in[6];
    const float* bih2  = (const float*)d_in[7];
    const float* bhh2  = (const float*)d_in[8];
    const float* Wout  = (const float*)d_in[9];
    const float* bout  = (const float*)d_in[10];

    int smem_bytes = SMEM_FLOATS * (int)sizeof(float);  // ~150 KB
    cudaFuncSetAttribute(lstm_persistent,
                         cudaFuncAttributeMaxDynamicSharedMemorySize, smem_bytes);

    lstm_persistent<<<NCTA, NTHREADS, smem_bytes>>>(
        input, Wih1, Whh1, bih1, bhh1, Wih2, Whh2, bih2, bhh2);

    // one warp per (t,b): T*B warps = 131072 -> 16384 blocks of 8 warps
    out_kernel<<<(T_STEPS * BATCH) / 8, 256>>>(Wout, bout, (float*)d_out);
}

// round 3
// speedup vs baseline: 1.0007x; 1.0007x over previous
#include <cuda_runtime.h>
#include <math.h>

// ---------------- problem constants ----------------
#define T_STEPS 2048
#define BATCH   64
#define IN_DIM  256
#define HID     512
#define NCTA    128      // 512 hidden units / 4 per CTA; all resident on 152-SM GB300
#define NTHREADS 256     // 8 warps, K-split across warps
#define NWARP   8

// SMEM row strides (floats), padded for bank behavior + 16B alignment
#define S1 772           // Wcat1: 768 cols (W_ih1 | W_hh1)
#define S2 1028          // Wcat2: 1024 cols (W_ih2 | W_hh2)

// dynamic smem layout (in floats)
//  ws1   : 16*S1      = 12352
//  ws2   : 16*S2      = 16448
//  stage : 8*16*64    = 8192
//  bias1 : 16, bias2 : 16, c1 : 256, c2 : 256
#define SMEM_FLOATS (16*S1 + 16*S2 + 8*16*64 + 16 + 16 + 256 + 256)

// ---------------- device scratch (static; no runtime allocation) ----------------
__device__ float g_h1slot[2][BATCH * HID];                     // double-buffered layer-1 h
__device__ float g_h2all[(size_t)T_STEPS * BATCH * HID];       // layer-2 h for all t (256MB)
__device__ unsigned g_count = 0;                               // barrier arrivals (self-resetting)
__device__ unsigned g_sense = 0;                               // barrier epoch (monotonic)

// ---------------- helpers ----------------
__device__ __forceinline__ unsigned ld_acq(unsigned* p) {
    unsigned v;
    asm volatile("ld.acquire.gpu.u32 %0, [%1];" : "=r"(v) : "l"(p));
    return v;
}

// packed fp32x2 FMA (FFMA2): 2 fp32 MACs/lane/inst -> 2x the FFMA-3reg rate
__device__ __forceinline__ void fma2(unsigned long long& d,
                                     unsigned long long a,
                                     unsigned long long b) {
    asm("fma.rn.f32x2 %0, %1, %2, %0;" : "+l"(d) : "l"(a), "l"(b));
}

// grid-wide barrier: sense-reversing, deterministic across graph replays
__device__ __forceinline__ void grid_barrier() {
    __syncthreads();
    if (threadIdx.x == 0) {
        unsigned s0 = ld_acq(&g_sense);
        __threadfence();                       // publish this CTA's global writes
        unsigned prev = atomicAdd(&g_count, 1);
        if (prev == NCTA - 1) {
            g_count = 0;                       // all arrived; reset for next use
            __threadfence();
            atomicAdd(&g_sense, 1);            // release
        } else {
            while (ld_acq(&g_sense) == s0) { } // acquire on release
        }
    }
    __syncthreads();
}

// accumulate: acc[i][bb] += sum_k src[b][k] * W[lr][k] over this call's k-range.
// src: global, row stride RS floats, already offset to the column base.
// wsm: smem,   row stride WS floats, already offset to the column base.
// lane tile: rows lr = rg*4+i (i<4), batches b = bg*8+bb (bb<8); nkq float4-quads.
__device__ __forceinline__ void accum(unsigned long long acc[4][8],
                                      const float* __restrict__ src, int RS,
                                      const float* wsm, int WS,
                                      int nkq, int rg, int bg) {
    const ulonglong2* hp[8];
    const ulonglong2* wp[4];
#pragma unroll
    for (int bb = 0; bb < 8; bb++)
        hp[bb] = reinterpret_cast<const ulonglong2*>(src + (size_t)(bg * 8 + bb) * RS);
#pragma unroll
    for (int i = 0; i < 4; i++)
        wp[i] = reinterpret_cast<const ulonglong2*>(wsm + (size_t)(rg * 4 + i) * WS);

#pragma unroll 4
    for (int kq = 0; kq < nkq; kq++) {
        ulonglong2 w[4], h[8];
#pragma unroll
        for (int i = 0; i < 4; i++) w[i] = wp[i][kq];
#pragma unroll
        for (int bb = 0; bb < 8; bb++) h[bb] = hp[bb][kq];
#pragma unroll
        for (int i = 0; i < 4; i++) {
#pragma unroll
            for (int bb = 0; bb < 8; bb++) {
                fma2(acc[i][bb], h[bb].x, w[i].x);
                fma2(acc[i][bb], h[bb].y, w[i].y);
            }
        }
    }
}

__device__ __forceinline__ float sigf(float x) { return 1.0f / (1.0f + expf(-x)); }

// ---------------- persistent fused 2-layer LSTM scan ----------------
__global__ void __launch_bounds__(NTHREADS, 1)
lstm_persistent(const float* __restrict__ input,
                const float* __restrict__ Wih1, const float* __restrict__ Whh1,
                const float* __restrict__ bih1, const float* __restrict__ bhh1,
                const float* __restrict__ Wih2, const float* __restrict__ Whh2,
                const float* __restrict__ bih2, const float* __restrict__ bhh2) {
    extern __shared__ float sm[];
    float* ws1   = sm;                          // 16 x S1
    float* ws2   = ws1 + 16 * S1;               // 16 x S2
    float* stage = ws2 + 16 * S2;               // 8 x 16 x 64
    float* bias1 = stage + 8 * 16 * 64;         // 16
    float* bias2 = bias1 + 16;                  // 16
    float* c1    = bias2 + 16;                  // 256
    float* c2    = c1 + 256;                    // 256

    const int tid  = threadIdx.x;
    const int cb   = blockIdx.x;
    const int j0   = cb * 4;                    // this CTA's 4 hidden units
    const int wid  = tid >> 5;
    const int lane = tid & 31;
    const int bg   = lane & 7;                  // batch group (8 batches)
    const int rg   = lane >> 3;                 // row group == gate index (4 rows)

    // ---- load weights + biases into SMEM (once) ----
    for (int lr = 0; lr < 16; lr++) {
        int grow = (lr >> 2) * HID + j0 + (lr & 3);   // gate*512 + j
        const float* a = Wih1 + (size_t)grow * IN_DIM;
        const float* b = Whh1 + (size_t)grow * HID;
        const float* c = Wih2 + (size_t)grow * HID;
        const float* d = Whh2 + (size_t)grow * HID;
        for (int k = tid; k < IN_DIM; k += NTHREADS) ws1[lr * S1 + k]          = a[k];
        for (int k = tid; k < HID;    k += NTHREADS) ws1[lr * S1 + IN_DIM + k] = b[k];
        for (int k = tid; k < HID;    k += NTHREADS) ws2[lr * S2 + k]          = c[k];
        for (int k = tid; k < HID;    k += NTHREADS) ws2[lr * S2 + HID + k]    = d[k];
    }
    if (tid < 16) {
        int grow = (tid >> 2) * HID + j0 + (tid & 3);
        bias1[tid] = bih1[grow] + bhh1[grow];
        bias2[tid] = bih2[grow] + bhh2[grow];
    }
    c1[tid] = 0.0f;
    c2[tid] = 0.0f;
    __syncthreads();

    for (int t = 0; t < T_STEPS; t++) {
        // ================= phase A: layer 1 =================
        unsigned long long acc[4][8];
#pragma unroll
        for (int i = 0; i < 4; i++)
#pragma unroll
            for (int bb = 0; bb < 8; bb++) acc[i][bb] = 0ull;

        // x_t part: K=256, warp chunk 32 cols
        accum(acc, input + (size_t)t * BATCH * IN_DIM + wid * 32, IN_DIM,
              ws1 + wid * 32, S1, 8, rg, bg);
        // h1_{t-1} part: K=512, warp chunk 64 cols
        if (t > 0)
            accum(acc, g_h1slot[(t - 1) & 1] + wid * 64, HID,
                  ws1 + IN_DIM + wid * 64, S1, 16, rg, bg);

#pragma unroll
        for (int i = 0; i < 4; i++)
#pragma unroll
            for (int bb = 0; bb < 8; bb++) {
                unsigned long long a = acc[i][bb];
                stage[(wid * 16 + rg * 4 + i) * 64 + bg * 8 + bb] =
                    __uint_as_float((unsigned)a) + __uint_as_float((unsigned)(a >> 32));
            }
        __syncthreads();

        {   // elementwise: one (jj, b) per thread
            int jj = tid >> 6, b = tid & 63;
            float gv[4];
#pragma unroll
            for (int g = 0; g < 4; g++) {
                float s = bias1[g * 4 + jj];
#pragma unroll
                for (int w = 0; w < NWARP; w++) s += stage[(w * 16 + g * 4 + jj) * 64 + b];
                gv[g] = s;
            }
            float c = c1[tid];
            c = sigf(gv[1]) * c + sigf(gv[0]) * tanhf(gv[2]);
            float h = sigf(gv[3]) * tanhf(c);
            c1[tid] = c;
            g_h1slot[t & 1][b * HID + j0 + jj] = h;
        }
        grid_barrier();

        // ================= phase B: layer 2 =================
#pragma unroll
        for (int i = 0; i < 4; i++)
#pragma unroll
            for (int bb = 0; bb < 8; bb++) acc[i][bb] = 0ull;

        // h1_t part: K=512
        accum(acc, g_h1slot[t & 1] + wid * 64, HID,
              ws2 + wid * 64, S2, 16, rg, bg);
        // h2_{t-1} part: K=512
        if (t > 0)
            accum(acc, g_h2all + ((size_t)(t - 1) * BATCH) * HID + wid * 64, HID,
                  ws2 + HID + wid * 64, S2, 16, rg, bg);

#pragma unroll
        for (int i = 0; i < 4; i++)
#pragma unroll
            for (int bb = 0; bb < 8; bb++) {
                unsigned long long a = acc[i][bb];
                stage[(wid * 16 + rg * 4 + i) * 64 + bg * 8 + bb] =
                    __uint_as_float((unsigned)a) + __uint_as_float((unsigned)(a >> 32));
            }
        __syncthreads();

        {
            int jj = tid >> 6, b = tid & 63;
            float gv[4];
#pragma unroll
            for (int g = 0; g < 4; g++) {
                float s = bias2[g * 4 + jj];
#pragma unroll
                for (int w = 0; w < NWARP; w++) s += stage[(w * 16 + g * 4 + jj) * 64 + b];
                gv[g] = s;
            }
            float c = c2[tid];
            c = sigf(gv[1]) * c + sigf(gv[0]) * tanhf(gv[2]);
            float h = sigf(gv[3]) * tanhf(c);
            c2[tid] = c;
            g_h2all[((size_t)t * BATCH + b) * HID + j0 + jj] = h;
        }
        grid_barrier();
    }
}

// ---------------- output head: out[t,b] = sigmoid(h2 . W_out + b_out) ----------------
__global__ void __launch_bounds__(256)
out_kernel(const float* __restrict__ Wout, const float* __restrict__ bout,
           float* __restrict__ out) {
    int gw   = (blockIdx.x * blockDim.x + threadIdx.x) >> 5;  // one warp per (t,b)
    int lane = threadIdx.x & 31;
    if (gw >= T_STEPS * BATCH) return;
    const float* h = g_h2all + (size_t)gw * HID;
    float s = 0.0f;
#pragma unroll
    for (int g = 0; g < 4; g++) {
        float4 hv = *reinterpret_cast<const float4*>(h + g * 128 + lane * 4);
        float4 wv = *reinterpret_cast<const float4*>(Wout + g * 128 + lane * 4);
        s += hv.x * wv.x + hv.y * wv.y + hv.z * wv.z + hv.w * wv.w;
    }
#pragma unroll
    for (int o = 16; o > 0; o >>= 1) s += __shfl_xor_sync(0xffffffffu, s, o);
    if (lane == 0) out[gw] = 1.0f / (1.0f + expf(-(s + bout[0])));
}

// ---------------- launch ----------------
extern "C" void kernel_launch(void* const* d_in, const int* in_sizes, int n_in,
                              void* d_out, int out_size) {
    const float* input = (const float*)d_in[0];
    const float* Wih1  = (const float*)d_in[1];
    const float* Whh1  = (const float*)d_in[2];
    const float* bih1  = (const float*)d_in[3];
    const float* bhh1  = (const float*)d_in[4];
    const float* Wih2  = (const float*)d_in[5];
    const float* Whh2  = (const float*)d_in[6];
    const float* bih2  = (const float*)d_in[7];
    const float* bhh2  = (const float*)d_in[8];
    const float* Wout  = (const float*)d_in[9];
    const float* bout  = (const float*)d_in[10];

    int smem_bytes = SMEM_FLOATS * (int)sizeof(float);  // ~150 KB
    cudaFuncSetAttribute(lstm_persistent,
                         cudaFuncAttributeMaxDynamicSharedMemorySize, smem_bytes);

    lstm_persistent<<<NCTA, NTHREADS, smem_bytes>>>(
        input, Wih1, Whh1, bih1, bhh1, Wih2, Whh2, bih2, bhh2);

    // one warp per (t,b): T*B warps = 131072 -> 16384 blocks of 8 warps
    out_kernel<<<(T_STEPS * BATCH) / 8, 256>>>(Wout, bout, (float*)d_out);
}

// round 4
// speedup vs baseline: 2.8673x; 2.8652x over previous
#include <cuda_runtime.h>
#include <math.h>

#define T_STEPS 2048
#define BATCH   64
#define IN_DIM  256
#define HID     512
#define NCTA    128
#define NTHREADS 512
#define NWARP   16
#define STAGE_S 66
#define SMEM_FLOATS (768*16 + 1024*16 + 256*STAGE_S + 16 + 16 + 256 + 256)

__device__ float g_xT [(size_t)T_STEPS * IN_DIM * BATCH];   // [t][k][b]
__device__ float g_h1T[2][HID * BATCH];                     // [slot][k][b]
__device__ float g_h2T[(size_t)T_STEPS * HID * BATCH];      // [t][k][b]
__device__ unsigned g_count = 0;
__device__ unsigned g_sense = 0;

__device__ __forceinline__ unsigned ld_acq(unsigned* p) {
    unsigned v; asm volatile("ld.acquire.gpu.u32 %0, [%1];" : "=r"(v) : "l"(p)); return v;
}
__device__ __forceinline__ void fma2(unsigned long long& d, unsigned long long a, unsigned long long b) {
    asm("fma.rn.f32x2 %0, %1, %2, %0;" : "+l"(d) : "l"(a), "l"(b));
}
__device__ __forceinline__ unsigned long long pk(float a, float b) {
    unsigned long long r; asm("mov.b64 %0, {%1, %2};" : "=l"(r) : "f"(a), "f"(b)); return r;
}
__device__ __forceinline__ unsigned long long dupf(float a) {
    unsigned long long r; asm("mov.b64 %0, {%1, %1};" : "=l"(r) : "f"(a)); return r;
}
__device__ __forceinline__ float sigf(float x) { return 1.0f / (1.0f + expf(-x)); }

__device__ __forceinline__ void grid_barrier() {
    __syncthreads();
    if (threadIdx.x == 0) {
        unsigned s0 = ld_acq(&g_sense);
        __threadfence();
        if (atomicAdd(&g_count, 1) == NCTA - 1) {
            g_count = 0; __threadfence(); atomicAdd(&g_sense, 1);
        } else {
            while (ld_acq(&g_sense) == s0) { }
        }
    }
    __syncthreads();
}

// hT: [k][64] global operand at this warp's k0; wsT: smem [k][16] at k0*16.
// lane: rg=lane>>3 picks 4 rows, bg=lane&7 picks 8 batches (4 packed pairs).
__device__ __forceinline__ void accum(unsigned long long acc[16],
                                      const float* __restrict__ hT,
                                      const float* wsT, int nk, int rg, int bg) {
    const float4* hp = reinterpret_cast<const float4*>(hT + bg * 8);
#pragma unroll 4
    for (int k = 0; k < nk; k++) {
        float4 w4 = *reinterpret_cast<const float4*>(wsT + k * 16 + rg * 4);
        float4 ha = __ldcg(hp + k * 16);
        float4 hb = __ldcg(hp + k * 16 + 1);
        unsigned long long h0 = pk(ha.x, ha.y), h1 = pk(ha.z, ha.w);
        unsigned long long h2 = pk(hb.x, hb.y), h3 = pk(hb.z, hb.w);
        unsigned long long w0 = dupf(w4.x), w1 = dupf(w4.y);
        unsigned long long w2 = dupf(w4.z), w3 = dupf(w4.w);
        fma2(acc[0],  h0, w0); fma2(acc[1],  h1, w0); fma2(acc[2],  h2, w0); fma2(acc[3],  h3, w0);
        fma2(acc[4],  h0, w1); fma2(acc[5],  h1, w1); fma2(acc[6],  h2, w1); fma2(acc[7],  h3, w1);
        fma2(acc[8],  h0, w2); fma2(acc[9],  h1, w2); fma2(acc[10], h2, w2); fma2(acc[11], h3, w2);
        fma2(acc[12], h0, w3); fma2(acc[13], h1, w3); fma2(acc[14], h2, w3); fma2(acc[15], h3, w3);
    }
}

__device__ __forceinline__ void dump_stage(float* stage, unsigned long long acc[16],
                                           int wid, int rg, int bg) {
#pragma unroll
    for (int i = 0; i < 4; i++) {
        float2* sp = reinterpret_cast<float2*>(stage + (wid * 16 + rg * 4 + i) * STAGE_S + bg * 8);
#pragma unroll
        for (int p = 0; p < 4; p++) {
            unsigned long long a = acc[i * 4 + p];
            sp[p] = make_float2(__uint_as_float((unsigned)a), __uint_as_float((unsigned)(a >> 32)));
        }
    }
}

// x[t][b][i] -> xT[t][i][b]
__global__ void __launch_bounds__(256)
transpose_x(const float* __restrict__ x) {
    __shared__ float tile[32][33];
    int t = blockIdx.z, i0 = blockIdx.x * 32, b0 = blockIdx.y * 32;
    int tx = threadIdx.x & 31, ty = threadIdx.x >> 5;   // 32 x 8
#pragma unroll
    for (int r = 0; r < 32; r += 8)
        tile[ty + r][tx] = x[((size_t)t * BATCH + b0 + ty + r) * IN_DIM + i0 + tx];
    __syncthreads();
#pragma unroll
    for (int r = 0; r < 32; r += 8)
        g_xT[((size_t)t * IN_DIM + i0 + ty + r) * BATCH + b0 + tx] = tile[tx][ty + r];
}

__global__ void __launch_bounds__(NTHREADS, 1)
lstm_persistent(const float* __restrict__ Wih1, const float* __restrict__ Whh1,
                const float* __restrict__ bih1, const float* __restrict__ bhh1,
                const float* __restrict__ Wih2, const float* __restrict__ Whh2,
                const float* __restrict__ bih2, const float* __restrict__ bhh2) {
    extern __shared__ float sm[];
    float* ws1T  = sm;                       // [768][16]
    float* ws2T  = ws1T + 768 * 16;          // [1024][16]
    float* stage = ws2T + 1024 * 16;         // [256][STAGE_S]
    float* bias1 = stage + 256 * STAGE_S;
    float* bias2 = bias1 + 16;
    float* c1    = bias2 + 16;
    float* c2    = c1 + 256;

    const int tid = threadIdx.x, j0 = blockIdx.x * 4;
    const int wid = tid >> 5, lane = tid & 31;
    const int bg = lane & 7, rg = lane >> 3;

    for (int lr = 0; lr < 16; lr++) {
        int grow = (lr >> 2) * HID + j0 + (lr & 3);
        const float* a = Wih1 + (size_t)grow * IN_DIM;
        const float* b = Whh1 + (size_t)grow * HID;
        const float* c = Wih2 + (size_t)grow * HID;
        const float* d = Whh2 + (size_t)grow * HID;
        for (int k = tid; k < IN_DIM; k += NTHREADS) ws1T[k * 16 + lr]            = a[k];
        for (int k = tid; k < HID;    k += NTHREADS) ws1T[(IN_DIM + k) * 16 + lr] = b[k];
        for (int k = tid; k < HID;    k += NTHREADS) ws2T[k * 16 + lr]            = c[k];
        for (int k = tid; k < HID;    k += NTHREADS) ws2T[(HID + k) * 16 + lr]    = d[k];
    }
    if (tid < 16) {
        int grow = (tid >> 2) * HID + j0 + (tid & 3);
        bias1[tid] = bih1[grow] + bhh1[grow];
        bias2[tid] = bih2[grow] + bhh2[grow];
    }
    if (tid < 256) { c1[tid] = 0.0f; c2[tid] = 0.0f; }
    __syncthreads();

    for (int t = 0; t < T_STEPS; t++) {
        unsigned long long acc[16];
        // ---- layer 1: K = 256 (xT) + 512 (h1T prev) ----
#pragma unroll
        for (int i = 0; i < 16; i++) acc[i] = 0ull;
        accum(acc, g_xT + (size_t)t * IN_DIM * BATCH + (size_t)(wid * 16) * BATCH,
              ws1T + (wid * 16) * 16, 16, rg, bg);
        if (t > 0)
            accum(acc, g_h1T[(t - 1) & 1] + (size_t)(wid * 32) * BATCH,
                  ws1T + (IN_DIM + wid * 32) * 16, 32, rg, bg);
        dump_stage(stage, acc, wid, rg, bg);
        __syncthreads();
        if (tid < 256) {
            int jj = tid >> 6, b = tid & 63;
            float gv[4];
#pragma unroll
            for (int g = 0; g < 4; g++) {
                float s = bias1[g * 4 + jj];
#pragma unroll
                for (int w = 0; w < NWARP; w++) s += stage[(w * 16 + g * 4 + jj) * STAGE_S + b];
                gv[g] = s;
            }
            float c = sigf(gv[1]) * c1[tid] + sigf(gv[0]) * tanhf(gv[2]);
            c1[tid] = c;
            g_h1T[t & 1][(size_t)(j0 + jj) * BATCH + b] = sigf(gv[3]) * tanhf(c);
        }
        grid_barrier();

        // ---- layer 2: K = 512 (h1T cur) + 512 (h2T prev) ----
#pragma unroll
        for (int i = 0; i < 16; i++) acc[i] = 0ull;
        accum(acc, g_h1T[t & 1] + (size_t)(wid * 32) * BATCH,
              ws2T + (wid * 32) * 16, 32, rg, bg);
        if (t > 0)
            accum(acc, g_h2T + ((size_t)(t - 1) * HID + wid * 32) * BATCH,
                  ws2T + (HID + wid * 32) * 16, 32, rg, bg);
        dump_stage(stage, acc, wid, rg, bg);
        __syncthreads();
        if (tid < 256) {
            int jj = tid >> 6, b = tid & 63;
            float gv[4];
#pragma unroll
            for (int g = 0; g < 4; g++) {
                float s = bias2[g * 4 + jj];
#pragma unroll
                for (int w = 0; w < NWARP; w++) s += stage[(w * 16 + g * 4 + jj) * STAGE_S + b];
                gv[g] = s;
            }
            float c = sigf(gv[1]) * c2[tid] + sigf(gv[0]) * tanhf(gv[2]);
            c2[tid] = c;
            g_h2T[((size_t)t * HID + j0 + jj) * BATCH + b] = sigf(gv[3]) * tanhf(c);
        }
        grid_barrier();
    }
}

// out[t][b] = sigmoid(sum_j h2T[t][j][b] * Wout[j] + bout)
__global__ void __launch_bounds__(512)
out_kernel(const float* __restrict__ Wout, const float* __restrict__ bout,
           float* __restrict__ out) {
    __shared__ float wsm[HID];
    __shared__ float red[8][66];
    int t = blockIdx.x, tid = threadIdx.x;
    int jg = tid >> 6, b = tid & 63;
    if (tid < HID) wsm[tid] = Wout[tid];
    __syncthreads();
    const float* h = g_h2T + ((size_t)t * HID + jg * 64) * BATCH + b;
    float s = 0.0f;
#pragma unroll 8
    for (int j = 0; j < 64; j++) s += h[(size_t)j * BATCH] * wsm[jg * 64 + j];
    red[jg][b] = s;
    __syncthreads();
    if (tid < 64) {
        float acc = bout[0];
#pragma unroll
        for (int g = 0; g < 8; g++) acc += red[g][tid];
        out[(size_t)t * BATCH + tid] = 1.0f / (1.0f + expf(-acc));
    }
}

extern "C" void kernel_launch(void* const* d_in, const int* in_sizes, int n_in,
                              void* d_out, int out_size) {
    const float* input = (const float*)d_in[0];
    const float* Wih1 = (const float*)d_in[1];
    const float* Whh1 = (const float*)d_in[2];
    const float* bih1 = (const float*)d_in[3];
    const float* bhh1 = (const float*)d_in[4];
    const float* Wih2 = (const float*)d_in[5];
    const float* Whh2 = (const float*)d_in[6];
    const float* bih2 = (const float*)d_in[7];
    const float* bhh2 = (const float*)d_in[8];
    const float* Wout = (const float*)d_in[9];
    const float* bout = (const float*)d_in[10];

    transpose_x<<<dim3(IN_DIM / 32, BATCH / 32, T_STEPS), 256>>>(input);

    int smem_bytes = SMEM_FLOATS * (int)sizeof(float);   // ~184 KB
    cudaFuncSetAttribute(lstm_persistent,
                         cudaFuncAttributeMaxDynamicSharedMemorySize, smem_bytes);
    lstm_persistent<<<NCTA, NTHREADS, smem_bytes>>>(
        Wih1, Whh1, bih1, bhh1, Wih2, Whh2, bih2, bhh2);

    out_kernel<<<T_STEPS, 512>>>(Wout, bout, (float*)d_out);
}

// round 5
// speedup vs baseline: 3.1838x; 1.1104x over previous
#include <cuda_runtime.h>
#include <math.h>

#define T_STEPS 2048
#define BATCH   64
#define IN_DIM  256
#define HID     512
#define NCTA    128
#define NTHREADS 512
#define NWARP   16
#define STAGE_S 66

// smem floats: ws1T 768*16, ws2T 1024*16, stage 256*STAGE_S,
//              bias1 16, bias2 16, c1 256, c2 256, wout 4, outred 4*66
#define SMEM_FLOATS (768*16 + 1024*16 + 256*STAGE_S + 16 + 16 + 256 + 256 + 4 + 4*66)

__device__ float g_xT [(size_t)T_STEPS * IN_DIM * BATCH];   // [t][k][b]
__device__ float g_h1T[2][HID * BATCH];                     // [slot][k][b]
__device__ float g_h2T[2][HID * BATCH];                     // [slot][k][b]
__device__ float g_outacc[T_STEPS * BATCH];
__device__ unsigned g_c1, g_s1, g_c2, g_s2;

__device__ __forceinline__ unsigned ld_acq(unsigned* p) {
    unsigned v; asm volatile("ld.acquire.gpu.u32 %0, [%1];" : "=r"(v) : "l"(p)); return v;
}
__device__ __forceinline__ void fma2(unsigned long long& d, unsigned long long a, unsigned long long b) {
    asm("fma.rn.f32x2 %0, %1, %2, %0;" : "+l"(d) : "l"(a), "l"(b));
}
__device__ __forceinline__ unsigned long long pk(float a, float b) {
    unsigned long long r; asm("mov.b64 %0, {%1, %2};" : "=l"(r) : "f"(a), "f"(b)); return r;
}
__device__ __forceinline__ unsigned long long dupf(float a) {
    unsigned long long r; asm("mov.b64 %0, {%1, %1};" : "=l"(r) : "f"(a)); return r;
}
// fast transcendentals (MUFU): err ~1e-6, well under 1e-3 budget
__device__ __forceinline__ float fex2(float x) { float r; asm("ex2.approx.f32 %0, %1;" : "=f"(r) : "f"(x)); return r; }
__device__ __forceinline__ float frcp(float x) { float r; asm("rcp.approx.f32 %0, %1;" : "=f"(r) : "f"(x)); return r; }
__device__ __forceinline__ float fsig(float x)  { return frcp(1.0f + fex2(-1.4426950408889634f * x)); }
__device__ __forceinline__ float ftanh(float x) { return fmaf(2.0f, frcp(1.0f + fex2(-2.8853900817779268f * x)), -1.0f); }

// non-blocking arrive / blocking wait (sense = steps completed, reset each launch)
__device__ __forceinline__ void bar_arrive(unsigned* cnt, unsigned* sense) {
    if (threadIdx.x == 0) {
        __threadfence();
        if (atomicAdd(cnt, 1) == NCTA - 1) { *cnt = 0; __threadfence(); atomicAdd(sense, 1); }
    }
}
__device__ __forceinline__ void bar_wait(unsigned* sense, unsigned target) {
    if (threadIdx.x == 0) { while (ld_acq(sense) < target) { } }
    __syncthreads();
}

// hT: [k][64] global at this warp's k0; wsT: smem [k][16] at k0*16.
__device__ __forceinline__ void accum(unsigned long long acc[16],
                                      const float* __restrict__ hT,
                                      const float* wsT, int nk, int rg, int bg) {
    const float4* hp = reinterpret_cast<const float4*>(hT + bg * 8);
#pragma unroll 4
    for (int k = 0; k < nk; k++) {
        float4 w4 = *reinterpret_cast<const float4*>(wsT + k * 16 + rg * 4);
        float4 ha = __ldcg(hp + k * 16);
        float4 hb = __ldcg(hp + k * 16 + 1);
        unsigned long long h0 = pk(ha.x, ha.y), h1 = pk(ha.z, ha.w);
        unsigned long long h2 = pk(hb.x, hb.y), h3 = pk(hb.z, hb.w);
        unsigned long long w0 = dupf(w4.x), w1 = dupf(w4.y);
        unsigned long long w2 = dupf(w4.z), w3 = dupf(w4.w);
        fma2(acc[0],  h0, w0); fma2(acc[1],  h1, w0); fma2(acc[2],  h2, w0); fma2(acc[3],  h3, w0);
        fma2(acc[4],  h0, w1); fma2(acc[5],  h1, w1); fma2(acc[6],  h2, w1); fma2(acc[7],  h3, w1);
        fma2(acc[8],  h0, w2); fma2(acc[9],  h1, w2); fma2(acc[10], h2, w2); fma2(acc[11], h3, w2);
        fma2(acc[12], h0, w3); fma2(acc[13], h1, w3); fma2(acc[14], h2, w3); fma2(acc[15], h3, w3);
    }
}

__device__ __forceinline__ void dump_stage(float* stage, unsigned long long acc[16],
                                           int wid, int rg, int bg) {
#pragma unroll
    for (int i = 0; i < 4; i++) {
        float2* sp = reinterpret_cast<float2*>(stage + (wid * 16 + rg * 4 + i) * STAGE_S + bg * 8);
#pragma unroll
        for (int p = 0; p < 4; p++) {
            unsigned long long a = acc[i * 4 + p];
            sp[p] = make_float2(__uint_as_float((unsigned)a), __uint_as_float((unsigned)(a >> 32)));
        }
    }
}

// x[t][b][i] -> xT[t][i][b]
__global__ void __launch_bounds__(256)
transpose_x(const float* __restrict__ x) {
    __shared__ float tile[32][33];
    int t = blockIdx.z, i0 = blockIdx.x * 32, b0 = blockIdx.y * 32;
    int tx = threadIdx.x & 31, ty = threadIdx.x >> 5;
#pragma unroll
    for (int r = 0; r < 32; r += 8)
        tile[ty + r][tx] = x[((size_t)t * BATCH + b0 + ty + r) * IN_DIM + i0 + tx];
    __syncthreads();
#pragma unroll
    for (int r = 0; r < 32; r += 8)
        g_xT[((size_t)t * IN_DIM + i0 + ty + r) * BATCH + b0 + tx] = tile[tx][ty + r];
}

// per-launch reset: zero out-accumulator + barrier state (graph-replay determinism)
__global__ void __launch_bounds__(256)
init_state() {
    int i = blockIdx.x * 256 + threadIdx.x;
    g_outacc[i] = 0.0f;
    if (i == 0) { g_c1 = 0; g_s1 = 0; g_c2 = 0; g_s2 = 0; }
}

__global__ void __launch_bounds__(NTHREADS, 1)
lstm_persistent(const float* __restrict__ Wih1, const float* __restrict__ Whh1,
                const float* __restrict__ bih1, const float* __restrict__ bhh1,
                const float* __restrict__ Wih2, const float* __restrict__ Whh2,
                const float* __restrict__ bih2, const float* __restrict__ bhh2,
                const float* __restrict__ Wout) {
    extern __shared__ float sm[];
    float* ws1T   = sm;                        // [768][16]
    float* ws2T   = ws1T + 768 * 16;           // [1024][16]
    float* stage  = ws2T + 1024 * 16;          // [256][STAGE_S]
    float* bias1  = stage + 256 * STAGE_S;
    float* bias2  = bias1 + 16;
    float* c1     = bias2 + 16;
    float* c2     = c1 + 256;
    float* wout_s = c2 + 256;                  // [4]
    float* outred = wout_s + 4;                // [4][66]

    const int tid = threadIdx.x, j0 = blockIdx.x * 4;
    const int wid = tid >> 5, lane = tid & 31;
    const int bg = lane & 7, rg = lane >> 3;

    for (int lr = 0; lr < 16; lr++) {
        int grow = (lr >> 2) * HID + j0 + (lr & 3);
        const float* a = Wih1 + (size_t)grow * IN_DIM;
        const float* b = Whh1 + (size_t)grow * HID;
        const float* c = Wih2 + (size_t)grow * HID;
        const float* d = Whh2 + (size_t)grow * HID;
        for (int k = tid; k < IN_DIM; k += NTHREADS) ws1T[k * 16 + lr]            = a[k];
        for (int k = tid; k < HID;    k += NTHREADS) ws1T[(IN_DIM + k) * 16 + lr] = b[k];
        for (int k = tid; k < HID;    k += NTHREADS) ws2T[k * 16 + lr]            = c[k];
        for (int k = tid; k < HID;    k += NTHREADS) ws2T[(HID + k) * 16 + lr]    = d[k];
    }
    if (tid < 16) {
        int grow = (tid >> 2) * HID + j0 + (tid & 3);
        bias1[tid] = bih1[grow] + bhh1[grow];
        bias2[tid] = bih2[grow] + bhh2[grow];
    }
    if (tid < 256) { c1[tid] = 0.0f; c2[tid] = 0.0f; }
    if (tid < 4) wout_s[tid] = Wout[j0 + tid];
    __syncthreads();

    unsigned long long acc1[16], acc2[16];
#pragma unroll
    for (int i = 0; i < 16; i++) acc1[i] = 0ull;
    // prologue: x(0) contribution (independent of any barrier)
    accum(acc1, g_xT + (size_t)(wid * 16) * BATCH, ws1T + (wid * 16) * 16, 16, rg, bg);

    for (int t = 0; t < T_STEPS; t++) {
        // ---- finish layer-1 gates: h1(t-1) contribution ----
        if (t > 0)
            accum(acc1, g_h1T[(t - 1) & 1] + (size_t)(wid * 32) * BATCH,
                  ws1T + (IN_DIM + wid * 32) * 16, 32, rg, bg);
        dump_stage(stage, acc1, wid, rg, bg);
        __syncthreads();
        if (tid < 256) {
            int jj = tid >> 6, b = tid & 63;
            float gv[4];
#pragma unroll
            for (int g = 0; g < 4; g++) {
                float s = bias1[g * 4 + jj];
#pragma unroll
                for (int w = 0; w < NWARP; w++) s += stage[(w * 16 + g * 4 + jj) * STAGE_S + b];
                gv[g] = s;
            }
            float c = fsig(gv[1]) * c1[tid] + fsig(gv[0]) * ftanh(gv[2]);
            c1[tid] = c;
            g_h1T[t & 1][(size_t)(j0 + jj) * BATCH + b] = fsig(gv[3]) * ftanh(c);
        }
        __syncthreads();
        bar_arrive(&g_c1, &g_s1);              // publish h1(t), don't block

        // ---- layer-2 independent part: h2(t-1) contribution (hides bar1 wait) ----
#pragma unroll
        for (int i = 0; i < 16; i++) acc2[i] = 0ull;
        if (t > 0)
            accum(acc2, g_h2T[(t - 1) & 1] + (size_t)(wid * 32) * BATCH,
                  ws2T + (HID + wid * 32) * 16, 32, rg, bg);
        bar_wait(&g_s1, (unsigned)(t + 1));    // h1(t) from all CTAs now visible

        // ---- layer-2 dependent part: h1(t) contribution ----
        accum(acc2, g_h1T[t & 1] + (size_t)(wid * 32) * BATCH,
              ws2T + (wid * 32) * 16, 32, rg, bg);
        dump_stage(stage, acc2, wid, rg, bg);
        __syncthreads();
        if (tid < 256) {
            int jj = tid >> 6, b = tid & 63;
            float gv[4];
#pragma unroll
            for (int g = 0; g < 4; g++) {
                float s = bias2[g * 4 + jj];
#pragma unroll
                for (int w = 0; w < NWARP; w++) s += stage[(w * 16 + g * 4 + jj) * STAGE_S + b];
                gv[g] = s;
            }
            float c = fsig(gv[1]) * c2[tid] + fsig(gv[0]) * ftanh(gv[2]);
            c2[tid] = c;
            float h = fsig(gv[3]) * ftanh(c);
            g_h2T[t & 1][(size_t)(j0 + jj) * BATCH + b] = h;
            outred[jj * 66 + b] = h * wout_s[jj];   // fused output-head partial
        }
        __syncthreads();
        if (tid < 64) {                         // 4-way reduce then fire-and-forget RED
            float v = outred[tid] + outred[66 + tid] + outred[132 + tid] + outred[198 + tid];
            atomicAdd(&g_outacc[t * BATCH + tid], v);
        }
        bar_arrive(&g_c2, &g_s2);              // publish h2(t), don't block

        // ---- next step's independent part: x(t+1) (hides bar2 wait) ----
#pragma unroll
        for (int i = 0; i < 16; i++) acc1[i] = 0ull;
        if (t + 1 < T_STEPS)
            accum(acc1, g_xT + (size_t)(t + 1) * IN_DIM * BATCH + (size_t)(wid * 16) * BATCH,
                  ws1T + (wid * 16) * 16, 16, rg, bg);
        bar_wait(&g_s2, (unsigned)(t + 1));    // h2(t) from all CTAs now visible
    }
}

__global__ void __launch_bounds__(256)
finish_out(const float* __restrict__ bout, float* __restrict__ out) {
    int i = blockIdx.x * 256 + threadIdx.x;
    out[i] = fsig(g_outacc[i] + bout[0]);
}

extern "C" void kernel_launch(void* const* d_in, const int* in_sizes, int n_in,
                              void* d_out, int out_size) {
    const float* input = (const float*)d_in[0];
    const float* Wih1 = (const float*)d_in[1];
    const float* Whh1 = (const float*)d_in[2];
    const float* bih1 = (const float*)d_in[3];
    const float* bhh1 = (const float*)d_in[4];
    const float* Wih2 = (const float*)d_in[5];
    const float* Whh2 = (const float*)d_in[6];
    const float* bih2 = (const float*)d_in[7];
    const float* bhh2 = (const float*)d_in[8];
    const float* Wout = (const float*)d_in[9];
    const float* bout = (const float*)d_in[10];

    init_state<<<T_STEPS * BATCH / 256, 256>>>();
    transpose_x<<<dim3(IN_DIM / 32, BATCH / 32, T_STEPS), 256>>>(input);

    int smem_bytes = SMEM_FLOATS * (int)sizeof(float);   // ~186 KB
    cudaFuncSetAttribute(lstm_persistent,
                         cudaFuncAttributeMaxDynamicSharedMemorySize, smem_bytes);
    lstm_persistent<<<NCTA, NTHREADS, smem_bytes>>>(
        Wih1, Whh1, bih1, bhh1, Wih2, Whh2, bih2, bhh2, Wout);

    finish_out<<<T_STEPS * BATCH / 256, 256>>>(bout, (float*)d_out);
}